// round 13
// baseline (speedup 1.0000x reference)
#include <cuda_runtime.h>
#include <cuda_bf16.h>
#include <math.h>
#include <stdint.h>

// ---------------------------------------------------------------------------
// Problem constants
// ---------------------------------------------------------------------------
#define NMAX 20000
#define DHC  512            // H*C
#define CDIM 128
#define EMAXR 340000        // max edges per relation incl self loops

// ---------------------------------------------------------------------------
// Device scratch — single xl/xr buffers (~85 MB, matches passing runs)
// ---------------------------------------------------------------------------
__device__ __align__(16) float g_xl[(size_t)NMAX * DHC];
__device__ __align__(16) float g_xr[(size_t)NMAX * DHC];
__device__ __align__(16) float g_outA[(size_t)NMAX * CDIM];
__device__ __align__(16) float g_outB[(size_t)NMAX * CDIM];
__device__ __align__(16) float g_outC[(size_t)NMAX * CDIM];
__device__ int g_cnt3[3][NMAX];
__device__ int g_off3[3][NMAX + 1];
__device__ int g_cur3[3][NMAX];
__device__ int g_srcbuf3[3][EMAXR];

struct CsrArgs {
    const int* ei[3];
    int E[3];
    int n_extra[3];
    int n_dst[3];
};

// ---------------------------------------------------------------------------
// bf16 split helpers (x = hi + lo, two k-consecutive values per u32)
// ---------------------------------------------------------------------------
__device__ __forceinline__ void bsplit2(float x, float y, unsigned& h, unsigned& l)
{
    unsigned short hx = __bfloat16_as_ushort(__float2bfloat16_rn(x));
    unsigned short hy = __bfloat16_as_ushort(__float2bfloat16_rn(y));
    float rx = x - __bfloat162float(__ushort_as_bfloat16(hx));
    float ry = y - __bfloat162float(__ushort_as_bfloat16(hy));
    unsigned short lx = __bfloat16_as_ushort(__float2bfloat16_rn(rx));
    unsigned short ly = __bfloat16_as_ushort(__float2bfloat16_rn(ry));
    h = ((unsigned)hy << 16) | (unsigned)hx;
    l = ((unsigned)ly << 16) | (unsigned)lx;
}

__device__ __forceinline__ void mma_bf16(float* c, const unsigned* a, const unsigned* b)
{
    asm volatile(
        "mma.sync.aligned.m16n8k16.row.col.f32.bf16.bf16.f32 "
        "{%0,%1,%2,%3}, {%4,%5,%6,%7}, {%8,%9}, {%0,%1,%2,%3};"
        : "+f"(c[0]), "+f"(c[1]), "+f"(c[2]), "+f"(c[3])
        : "r"(a[0]), "r"(a[1]), "r"(a[2]), "r"(a[3]), "r"(b[0]), "r"(b[1]));
}

// ---------------------------------------------------------------------------
// Paired GEMM (bf16x3, scalar LDS — round-10 known-passing version).
// blockIdx.z = 0: g_xl = Xs @ Wl + bl ; z = 1: g_xr = Xd @ Wr + br.
// Block tile 128x128, BK=32, 256 thr, 8 warps (4x2), warp tile 32x64.
// Smem: A [row][kp] u32 stride 20, B [col][kp] u32 stride 20.
// ---------------------------------------------------------------------------
#define GBM 128
#define PSTR 20

__global__ __launch_bounds__(256) void gemm_pair_kernel(
    const float* __restrict__ Xl, const float* __restrict__ Wl,
    const float* __restrict__ bl, int Ml,
    const float* __restrict__ Xr, const float* __restrict__ Wr,
    const float* __restrict__ br, int Mr)
{
    __shared__ unsigned AhP[128 * PSTR], AlP[128 * PSTR];
    __shared__ unsigned BhP[128 * PSTR], BlP[128 * PSTR];

    int z = blockIdx.z;
    const float* __restrict__ X = z ? Xr : Xl;
    const float* __restrict__ W = z ? Wr : Wl;
    const float* __restrict__ bias = z ? br : bl;
    int M = z ? Mr : Ml;
    float* out = z ? g_xr : g_xl;

    int tid = threadIdx.x;
    int m0 = blockIdx.x * GBM;
    if (m0 >= M) return;
    int n0 = blockIdx.y * 128;
    int w = tid >> 5, lane = tid & 31;
    int wm = (w & 3) * 32;
    int wn = (w >> 2) * 64;
    int g = lane >> 2, tg = lane & 3;

    float c[2][8][4];
#pragma unroll
    for (int mt = 0; mt < 2; mt++)
#pragma unroll
        for (int nt = 0; nt < 8; nt++)
#pragma unroll
            for (int i = 0; i < 4; i++) c[mt][nt][i] = 0.f;

    for (int kc = 0; kc < 4; kc++) {
        // A slab: 128 rows x 32 k = 1024 float4; 4 per thread.
#pragma unroll
        for (int i = 0; i < 4; i++) {
            int idx = tid + i * 256;
            int r = idx >> 3, f4 = idx & 7;
            float4 v = make_float4(0.f, 0.f, 0.f, 0.f);
            if (m0 + r < M)
                v = *(const float4*)(X + (size_t)(m0 + r) * 128 + kc * 32 + f4 * 4);
            unsigned h0, l0, h1, l1;
            bsplit2(v.x, v.y, h0, l0);
            bsplit2(v.z, v.w, h1, l1);
            int base = r * PSTR + f4 * 2;
            AhP[base] = h0; AhP[base + 1] = h1;
            AlP[base] = l0; AlP[base + 1] = l1;
        }
        // B slab: 32 k x 128 n -> B[col][kp]
#pragma unroll
        for (int i = 0; i < 2; i++) {
            int idx = tid + i * 256;
            int kp = idx & 15, c4 = idx >> 4;
            int krow = kc * 32 + kp * 2;
            float4 v0 = *(const float4*)(W + (size_t)krow * 512 + n0 + c4 * 4);
            float4 v1 = *(const float4*)(W + (size_t)(krow + 1) * 512 + n0 + c4 * 4);
            unsigned h, l;
            bsplit2(v0.x, v1.x, h, l);
            BhP[(c4 * 4 + 0) * PSTR + kp] = h; BlP[(c4 * 4 + 0) * PSTR + kp] = l;
            bsplit2(v0.y, v1.y, h, l);
            BhP[(c4 * 4 + 1) * PSTR + kp] = h; BlP[(c4 * 4 + 1) * PSTR + kp] = l;
            bsplit2(v0.z, v1.z, h, l);
            BhP[(c4 * 4 + 2) * PSTR + kp] = h; BlP[(c4 * 4 + 2) * PSTR + kp] = l;
            bsplit2(v0.w, v1.w, h, l);
            BhP[(c4 * 4 + 3) * PSTR + kp] = h; BlP[(c4 * 4 + 3) * PSTR + kp] = l;
        }
        __syncthreads();

#pragma unroll
        for (int ks = 0; ks < 2; ks++) {
            int kp0 = ks * 8;
            unsigned ah[2][4], al[2][4];
#pragma unroll
            for (int mt = 0; mt < 2; mt++) {
                int row = wm + mt * 16;
                ah[mt][0] = AhP[(row + g)     * PSTR + kp0 + tg];
                ah[mt][1] = AhP[(row + g + 8) * PSTR + kp0 + tg];
                ah[mt][2] = AhP[(row + g)     * PSTR + kp0 + tg + 4];
                ah[mt][3] = AhP[(row + g + 8) * PSTR + kp0 + tg + 4];
                al[mt][0] = AlP[(row + g)     * PSTR + kp0 + tg];
                al[mt][1] = AlP[(row + g + 8) * PSTR + kp0 + tg];
                al[mt][2] = AlP[(row + g)     * PSTR + kp0 + tg + 4];
                al[mt][3] = AlP[(row + g + 8) * PSTR + kp0 + tg + 4];
            }
#pragma unroll
            for (int nt = 0; nt < 8; nt++) {
                int col = wn + nt * 8 + g;
                unsigned bh[2], bl2[2];
                bh[0]  = BhP[col * PSTR + kp0 + tg];
                bh[1]  = BhP[col * PSTR + kp0 + tg + 4];
                bl2[0] = BlP[col * PSTR + kp0 + tg];
                bl2[1] = BlP[col * PSTR + kp0 + tg + 4];
#pragma unroll
                for (int mt = 0; mt < 2; mt++) {
                    mma_bf16(c[mt][nt], ah[mt], bh);
                    mma_bf16(c[mt][nt], ah[mt], bl2);
                    mma_bf16(c[mt][nt], al[mt], bh);
                }
            }
        }
        __syncthreads();
    }

#pragma unroll
    for (int mt = 0; mt < 2; mt++) {
#pragma unroll
        for (int nt = 0; nt < 8; nt++) {
            int col = n0 + wn + nt * 8 + tg * 2;
            float b0 = __ldg(bias + col);
            float b1 = __ldg(bias + col + 1);
            int row0 = m0 + wm + mt * 16 + g;
            if (row0 < M) {
                float2 v0 = make_float2(c[mt][nt][0] + b0, c[mt][nt][1] + b1);
                *(float2*)(out + (size_t)row0 * 512 + col) = v0;
            }
            int row1 = row0 + 8;
            if (row1 < M) {
                float2 v1 = make_float2(c[mt][nt][2] + b0, c[mt][nt][3] + b1);
                *(float2*)(out + (size_t)row1 * 512 + col) = v1;
            }
        }
    }
}

// ---------------------------------------------------------------------------
// Fused CSR build (all relations)
// ---------------------------------------------------------------------------
__global__ void zero_all_kernel(int n0, int n1, int n2)
{
    int i = blockIdx.x * blockDim.x + threadIdx.x;
    if (i < n0) g_cnt3[0][i] = 0;
    if (i < n1) g_cnt3[1][i] = 0;
    if (i < n2) g_cnt3[2][i] = 0;
}

__global__ void hist_all_kernel(CsrArgs a)
{
    int rel = blockIdx.y;
    int idx = blockIdx.x * blockDim.x + threadIdx.x;
    int E = a.E[rel];
    if (idx >= E + a.n_extra[rel]) return;
    int d = (idx < E) ? a.ei[rel][E + idx] : (idx - E);
    if (d >= 0 && d < a.n_dst[rel]) atomicAdd(&g_cnt3[rel][d], 1);
}

__global__ void scan_all_kernel(int nd0, int nd1, int nd2)
{
    __shared__ int sh[1024];
    __shared__ int s_carry;
    int rel = blockIdx.x;
    int n = (rel == 0) ? nd0 : (rel == 1) ? nd1 : nd2;
    int tid = threadIdx.x;
    if (tid == 0) s_carry = 0;
    __syncthreads();
    for (int base = 0; base < n; base += 1024) {
        int i = base + tid;
        int v = (i < n) ? g_cnt3[rel][i] : 0;
        sh[tid] = v;
        __syncthreads();
        for (int off = 1; off < 1024; off <<= 1) {
            int t = (tid >= off) ? sh[tid - off] : 0;
            __syncthreads();
            sh[tid] += t;
            __syncthreads();
        }
        int incl = sh[tid];
        int excl = incl - v + s_carry;
        if (i < n) { g_off3[rel][i] = excl; g_cur3[rel][i] = excl; }
        __syncthreads();
        if (tid == 1023) s_carry += incl;
        __syncthreads();
    }
    if (tid == 0) g_off3[rel][n] = s_carry;
}

__global__ void scatter_all_kernel(CsrArgs a)
{
    int rel = blockIdx.y;
    int idx = blockIdx.x * blockDim.x + threadIdx.x;
    int E = a.E[rel];
    if (idx >= E + a.n_extra[rel]) return;
    int s, d;
    if (idx < E) { s = a.ei[rel][idx]; d = a.ei[rel][E + idx]; }
    else         { s = d = idx - E; }
    if (d < 0 || d >= a.n_dst[rel]) return;
    int pos = atomicAdd(&g_cur3[rel][d], 1);
    if (pos >= 0 && pos < EMAXR) g_srcbuf3[rel][pos] = s;
}

// ---------------------------------------------------------------------------
// GATv2 edge kernel v2: TWO warps per dst node, 2 heads per warp,
// online softmax per head, 2-deep gather prefetch, smem head-combine.
// ---------------------------------------------------------------------------
__global__ __launch_bounds__(256) void edge_kernel(
    const float* __restrict__ att, const float* __restrict__ bias,
    int rel, int n_dst)
{
    __shared__ float4 s_part[4][32];

    int tid = threadIdx.x, warp = tid >> 5, lane = tid & 31;
    int slot = warp >> 1;     // 0..3: dst within block
    int hh = warp & 1;        // 0: heads 0,1 ; 1: heads 2,3
    int d = blockIdx.x * 4 + slot;
    float* out = (rel == 0) ? g_outA : (rel == 1) ? g_outB : g_outC;

    float4 po = make_float4(0.f, 0.f, 0.f, 0.f);

    if (d < n_dst) {
        const int* srcbuf = g_srcbuf3[rel];
        int q0 = 2 * hh, q1 = 2 * hh + 1;
        int o0 = q0 * 32 + lane, o1 = q1 * 32 + lane;

        const float4* xr4p = (const float4*)(g_xr + (size_t)d * DHC);
        const float4* att4p = (const float4*)att;
        float4 xr0 = xr4p[o0], xr1 = xr4p[o1];
        float4 at0 = att4p[o0], at1 = att4p[o1];
        float4 acc0 = make_float4(0.f, 0.f, 0.f, 0.f);
        float4 acc1 = make_float4(0.f, 0.f, 0.f, 0.f);
        float m0 = -INFINITY, m1 = -INFINITY, den0 = 0.f, den1 = 0.f;

        int j = g_off3[rel][d], end = g_off3[rel][d + 1];
        float4 na0, na1, nb0, nb1;
        if (j < end) {
            const float4* p = (const float4*)(g_xl + (size_t)srcbuf[j] * DHC);
            na0 = p[o0]; na1 = p[o1];
        }
        if (j + 1 < end) {
            const float4* p = (const float4*)(g_xl + (size_t)srcbuf[j + 1] * DHC);
            nb0 = p[o0]; nb1 = p[o1];
        }
        while (j < end) {
            float4 xl0 = na0, xl1 = na1;
            na0 = nb0; na1 = nb1;
            if (j + 2 < end) {
                const float4* p = (const float4*)(g_xl + (size_t)srcbuf[j + 2] * DHC);
                nb0 = p[o0]; nb1 = p[o1];
            }
            j++;

            float ex, ey, ez, ew, s0, s1;
            ex = xl0.x + xr0.x; ex = fmaxf(ex, 0.2f * ex);
            ey = xl0.y + xr0.y; ey = fmaxf(ey, 0.2f * ey);
            ez = xl0.z + xr0.z; ez = fmaxf(ez, 0.2f * ez);
            ew = xl0.w + xr0.w; ew = fmaxf(ew, 0.2f * ew);
            s0 = ex * at0.x + ey * at0.y + ez * at0.z + ew * at0.w;
            ex = xl1.x + xr1.x; ex = fmaxf(ex, 0.2f * ex);
            ey = xl1.y + xr1.y; ey = fmaxf(ey, 0.2f * ey);
            ez = xl1.z + xr1.z; ez = fmaxf(ez, 0.2f * ez);
            ew = xl1.w + xr1.w; ew = fmaxf(ew, 0.2f * ew);
            s1 = ex * at1.x + ey * at1.y + ez * at1.z + ew * at1.w;
#pragma unroll
            for (int o = 16; o; o >>= 1) {
                s0 += __shfl_xor_sync(0xffffffffu, s0, o);
                s1 += __shfl_xor_sync(0xffffffffu, s1, o);
            }
            {
                float mn = fmaxf(m0, s0);
                float sc = __expf(m0 - mn);
                float wg = __expf(s0 - mn);
                den0 = den0 * sc + wg;
                acc0.x = acc0.x * sc + wg * xl0.x;
                acc0.y = acc0.y * sc + wg * xl0.y;
                acc0.z = acc0.z * sc + wg * xl0.z;
                acc0.w = acc0.w * sc + wg * xl0.w;
                m0 = mn;
            }
            {
                float mn = fmaxf(m1, s1);
                float sc = __expf(m1 - mn);
                float wg = __expf(s1 - mn);
                den1 = den1 * sc + wg;
                acc1.x = acc1.x * sc + wg * xl1.x;
                acc1.y = acc1.y * sc + wg * xl1.y;
                acc1.z = acc1.z * sc + wg * xl1.z;
                acc1.w = acc1.w * sc + wg * xl1.w;
                m1 = mn;
            }
        }
        float i0 = (den0 > 0.f) ? 1.f / den0 : 0.f;
        float i1 = (den1 > 0.f) ? 1.f / den1 : 0.f;
        po.x = acc0.x * i0 + acc1.x * i1;
        po.y = acc0.y * i0 + acc1.y * i1;
        po.z = acc0.z * i0 + acc1.z * i1;
        po.w = acc0.w * i0 + acc1.w * i1;
    }

    if (hh == 1) s_part[slot][lane] = po;
    __syncthreads();
    if (hh == 0 && d < n_dst) {
        float4 o2 = s_part[slot][lane];
        float4 b4 = ((const float4*)bias)[lane];
        float4 o;
        o.x = (po.x + o2.x) * 0.25f + b4.x;
        o.y = (po.y + o2.y) * 0.25f + b4.y;
        o.z = (po.z + o2.z) * 0.25f + b4.z;
        o.w = (po.w + o2.w) * 0.25f + b4.w;
        ((float4*)(out + (size_t)d * CDIM))[lane] = o;
    }
}

// ---------------------------------------------------------------------------
// JAX threefry2x32 core
// ---------------------------------------------------------------------------
__device__ __forceinline__ void threefry2x32(
    unsigned k0, unsigned k1, unsigned x0, unsigned x1,
    unsigned& o0, unsigned& o1)
{
    unsigned ks2 = k0 ^ k1 ^ 0x1BD11BDAu;
    x0 += k0; x1 += k1;
#define TFR(r) { x0 += x1; x1 = (x1 << r) | (x1 >> (32 - r)); x1 ^= x0; }
    TFR(13) TFR(15) TFR(26) TFR(6)  x0 += k1;  x1 += ks2 + 1u;
    TFR(17) TFR(29) TFR(16) TFR(24) x0 += ks2; x1 += k0 + 2u;
    TFR(13) TFR(15) TFR(26) TFR(6)  x0 += k0;  x1 += k1 + 3u;
    TFR(17) TFR(29) TFR(16) TFR(24) x0 += k1;  x1 += ks2 + 4u;
    TFR(13) TFR(15) TFR(26) TFR(6)  x0 += ks2; x1 += k0 + 5u;
#undef TFR
    o0 = x0; o1 = x1;
}

// ---------------------------------------------------------------------------
// Fused epilogue for BOTH node types in one launch.
// ---------------------------------------------------------------------------
__global__ __launch_bounds__(256) void finalize_all_kernel(
    const float* __restrict__ x_rxn, const float* __restrict__ x_met,
    const float* __restrict__ gr, const float* __restrict__ br,
    const float* __restrict__ gm, const float* __restrict__ bm,
    float* __restrict__ out, int n_rxn, int n_met)
{
    int wg = (blockIdx.x * blockDim.x + threadIdx.x) >> 5;
    int lane = threadIdx.x & 31;
    if (wg >= n_rxn + n_met) return;

    int mode = (wg < n_rxn) ? 0 : 1;
    int w = (mode == 0) ? wg : wg - n_rxn;
    const float* xres = (mode == 0) ? x_rxn : x_met;
    const float* gamma = (mode == 0) ? gr : gm;
    const float* beta = (mode == 0) ? br : bm;
    unsigned key1 = (mode == 0) ? 101u : 202u;
    float* o_base = (mode == 0) ? out : out + (size_t)n_rxn * CDIM;

    const float4* A = (const float4*)((mode == 0) ? g_outA : g_outC);
    float4 v = A[(size_t)w * 32 + lane];
    if (mode == 0) {
        float4 b = ((const float4*)g_outB)[(size_t)w * 32 + lane];
        v.x = (v.x + b.x) * 0.5f; v.y = (v.y + b.y) * 0.5f;
        v.z = (v.z + b.z) * 0.5f; v.w = (v.w + b.w) * 0.5f;
    }
    v.x = (v.x > 0.f) ? v.x : expm1f(v.x);
    v.y = (v.y > 0.f) ? v.y : expm1f(v.y);
    v.z = (v.z > 0.f) ? v.z : expm1f(v.z);
    v.w = (v.w > 0.f) ? v.w : expm1f(v.w);
    float4 r = ((const float4*)xres)[(size_t)w * 32 + lane];
    v.x += r.x; v.y += r.y; v.z += r.z; v.w += r.w;
    float sum = v.x + v.y + v.z + v.w;
#pragma unroll
    for (int o = 16; o; o >>= 1) sum += __shfl_xor_sync(0xffffffffu, sum, o);
    float mu = sum * (1.f / 128.f);
    float4 c;
    c.x = v.x - mu; c.y = v.y - mu; c.z = v.z - mu; c.w = v.w - mu;
    float sq = c.x * c.x + c.y * c.y + c.z * c.z + c.w * c.w;
#pragma unroll
    for (int o = 16; o; o >>= 1) sq += __shfl_xor_sync(0xffffffffu, sq, o);
    float rs = rsqrtf(sq * (1.f / 128.f) + 1e-5f);
    float4 g4 = ((const float4*)gamma)[lane];
    float4 b4 = ((const float4*)beta)[lane];
    float y[4];
    y[0] = c.x * rs * g4.x + b4.x;
    y[1] = c.y * rs * g4.y + b4.y;
    y[2] = c.z * rs * g4.z + b4.z;
    y[3] = c.w * rs * g4.w + b4.w;
    unsigned base = (unsigned)w * 128u + (unsigned)lane * 4u;
#pragma unroll
    for (int cc = 0; cc < 4; cc++) {
        unsigned flat = base + cc;
        unsigned o0, o1;
        threefry2x32(0u, key1, 0u, flat, o0, o1);
        unsigned bits = o0 ^ o1;
        float u = __uint_as_float((bits >> 9) | 0x3f800000u) - 1.f;
        y[cc] = (u < 0.8f) ? (y[cc] / 0.8f) : 0.f;
    }
    float4 o4; o4.x = y[0]; o4.y = y[1]; o4.z = y[2]; o4.w = y[3];
    ((float4*)(o_base + (size_t)w * CDIM))[lane] = o4;
}

// ---------------------------------------------------------------------------
// Host launcher — gemm_pair(rel0) at launch index 3 (ncu capture slot)
// ---------------------------------------------------------------------------
extern "C" void kernel_launch(void* const* d_in, const int* in_sizes, int n_in,
                              void* d_out, int out_size)
{
    const float* x_met = (const float*)d_in[0];
    const float* x_rxn = (const float*)d_in[1];
    const int* ei_sub = (const int*)d_in[2];
    const int* ei_prod = (const int*)d_in[3];
    const int* ei_shared = (const int*)d_in[4];
    int n_met = in_sizes[0] / CDIM;
    int n_rxn = in_sizes[1] / CDIM;
    int E_sub = in_sizes[2] / 2;
    int E_prod = in_sizes[3] / 2;
    int E_shared = in_sizes[4] / 2;
    float* out = (float*)d_out;

    // relation order: 0=sub(met->rxn), 1=shared(rxn->rxn,+loops), 2=prod(rxn->met)
    const float* xs[3] = { x_met, x_rxn, x_rxn };
    const float* xd[3] = { x_rxn, x_rxn, x_met };
    int n_src[3] = { n_met, n_rxn, n_rxn };
    int n_dst[3] = { n_rxn, n_rxn, n_met };
    int baseidx[3] = { 5, 17, 11 };

    CsrArgs ca;
    ca.ei[0] = ei_sub;    ca.E[0] = E_sub;    ca.n_extra[0] = 0;     ca.n_dst[0] = n_rxn;
    ca.ei[1] = ei_shared; ca.E[1] = E_shared; ca.n_extra[1] = n_rxn; ca.n_dst[1] = n_rxn;
    ca.ei[2] = ei_prod;   ca.E[2] = E_prod;   ca.n_extra[2] = 0;     ca.n_dst[2] = n_met;

    int nmax_nodes = (n_rxn > n_met) ? n_rxn : n_met;
    int tot_max = 0;
    for (int r = 0; r < 3; r++) {
        int t = ca.E[r] + ca.n_extra[r];
        if (t > tot_max) tot_max = t;
    }

    // 0-2: CSR front half
    zero_all_kernel<<<(nmax_nodes + 255) / 256, 256>>>(ca.n_dst[0], ca.n_dst[1], ca.n_dst[2]);
    {
        dim3 g((tot_max + 255) / 256, 3);
        hist_all_kernel<<<g, 256>>>(ca);
    }
    scan_all_kernel<<<3, 1024>>>(ca.n_dst[0], ca.n_dst[1], ca.n_dst[2]);

    // 3: gemm_pair rel0 (ncu-captured launch)
    {
        int mmax = (n_src[0] > n_dst[0]) ? n_src[0] : n_dst[0];
        dim3 g((mmax + GBM - 1) / GBM, 4, 2);
        gemm_pair_kernel<<<g, 256>>>(xs[0], (const float*)d_in[baseidx[0] + 0],
                                     (const float*)d_in[baseidx[0] + 3], n_src[0],
                                     xd[0], (const float*)d_in[baseidx[0] + 1],
                                     (const float*)d_in[baseidx[0] + 4], n_dst[0]);
    }

    // 4: scatter (completes CSR)
    {
        dim3 g((tot_max + 255) / 256, 3);
        scatter_all_kernel<<<g, 256>>>(ca);
    }

    // 5: edge rel0
    edge_kernel<<<(n_dst[0] + 3) / 4, 256>>>(
        (const float*)d_in[baseidx[0] + 2], (const float*)d_in[baseidx[0] + 5],
        0, n_dst[0]);

    // 6-9: relations 1 and 2
    for (int r = 1; r < 3; r++) {
        int mmax = (n_src[r] > n_dst[r]) ? n_src[r] : n_dst[r];
        dim3 g((mmax + GBM - 1) / GBM, 4, 2);
        gemm_pair_kernel<<<g, 256>>>(xs[r], (const float*)d_in[baseidx[r] + 0],
                                     (const float*)d_in[baseidx[r] + 3], n_src[r],
                                     xd[r], (const float*)d_in[baseidx[r] + 1],
                                     (const float*)d_in[baseidx[r] + 4], n_dst[r]);
        edge_kernel<<<(n_dst[r] + 3) / 4, 256>>>(
            (const float*)d_in[baseidx[r] + 2], (const float*)d_in[baseidx[r] + 5],
            r, n_dst[r]);
    }

    // 10: fused finalize
    {
        int tw = n_rxn + n_met;
        finalize_all_kernel<<<(tw + 7) / 8, 256>>>(
            x_rxn, x_met,
            (const float*)d_in[23], (const float*)d_in[24],
            (const float*)d_in[25], (const float*)d_in[26],
            out, n_rxn, n_met);
    }
}